// round 1
// baseline (speedup 1.0000x reference)
#include <cuda_runtime.h>
#include <math.h>

#define K        8
#define D        256
#define C4       (D / 4)     // 64 float4 columns
#define TILE_N   64          // rows per block
#define RPT      16          // rows per thread (TILE_N / (THREADS/C4))
#define THREADS  256
#define NEGV     (-1e9f)

// valid_mask may arrive as int32 / uint8(bool) / float32 depending on how the
// harness lowers jnp.bool_. Detect once from word 0 (guaranteed "true" since
// lengths >= N/2).
__device__ __forceinline__ bool mask_at(const void* m, int fmt, long i) {
    if (fmt == 1) return ((const unsigned char*)m)[i] != 0;
    if (fmt == 2) return ((const float*)m)[i] != 0.0f;
    return ((const int*)m)[i] != 0;
}

__global__ __launch_bounds__(THREADS)
void mixer_kernel(const float* __restrict__ x,
                  const float* __restrict__ dts,
                  const void*  __restrict__ maskp,
                  const float* __restrict__ w,
                  const float* __restrict__ beta,
                  float* __restrict__ out,
                  int N)
{
    __shared__ float s_alpha[TILE_N * K];

    const int  b    = blockIdx.y;
    const int  n0   = blockIdx.x * TILE_N;
    const int  tid  = threadIdx.x;
    const long base = (long)b * N;

    // ---- mask format detection (uniform across grid) ----
    const unsigned int w0 = *((const unsigned int*)maskp);
    int fmt = 0;
    if (w0 == 0x01010101u)      fmt = 1;   // uint8 bool
    else if (w0 == 0x3F800000u) fmt = 2;   // float32

    // ================= Phase 1: alpha[TILE_N][K] =================
    if (tid < TILE_N) {
        const int  n      = n0 + tid;
        const bool valid0 = mask_at(maskp, fmt, base + n);
        const float dt0   = dts[base + n];

        float score[K];
        bool  cv[K];
        cv[0]    = valid0;
        score[0] = valid0 ? 0.0f : NEGV;
        #pragma unroll
        for (int p = 1; p < K; p++) {
            const int np = n + p;
            bool  c  = false;
            float td = 0.0f;
            if (np < N) {
                c = valid0 && mask_at(maskp, fmt, base + np);
                if (c) td = fmaxf(dts[base + np] - dt0, 0.0f);
            }
            cv[p]    = c;
            score[p] = c ? -td : NEGV;
        }

        // temporal-decay softmax over offsets
        float m = score[0];
        #pragma unroll
        for (int p = 1; p < K; p++) m = fmaxf(m, score[p]);
        float e[K], es = 0.0f;
        #pragma unroll
        for (int p = 0; p < K; p++) { e[p] = __expf(score[p] - m); es += e[p]; }
        const float inv_es = 1.0f / es;

        // softmax(w) and sigmoid(beta) — tiny, recompute per row
        float wv[K];
        #pragma unroll
        for (int p = 0; p < K; p++) wv[p] = w[p];
        float wm = wv[0];
        #pragma unroll
        for (int p = 1; p < K; p++) wm = fmaxf(wm, wv[p]);
        float we[K], ws = 0.0f;
        #pragma unroll
        for (int p = 0; p < K; p++) { we[p] = __expf(wv[p] - wm); ws += we[p]; }
        const float inv_ws = 1.0f / ws;
        const float bsig   = 1.0f / (1.0f + __expf(-beta[0]));
        const float omb    = 1.0f - bsig;

        float a[K], asum = 0.0f;
        #pragma unroll
        for (int p = 0; p < K; p++) {
            a[p] = cv[p] ? (bsig * we[p] * inv_ws + omb * e[p] * inv_es) : 0.0f;
            asum += a[p];
        }
        const float inv = 1.0f / fmaxf(asum, 1e-8f);
        #pragma unroll
        for (int p = 0; p < K; p++) s_alpha[tid * K + p] = a[p] * inv;
    }
    __syncthreads();

    // ================= Phase 2: weighted sliding-window sum =================
    const int c4     = tid & (C4 - 1);     // float4 column 0..63
    const int g      = tid >> 6;           // row-strip group 0..3
    const int r0     = g * RPT;            // local start row
    const int nstart = n0 + r0;

    const float4* __restrict__ xr =
        (const float4*)x + (base + nstart) * (long)C4 + c4;
    float4* __restrict__ orow =
        (float4*)out + (base + nstart) * (long)C4 + c4;

    // 8-deep register window of x rows at this column
    float4 win[K];
    #pragma unroll
    for (int j = 0; j < K; j++) {
        const int nr = nstart + j;
        win[j] = (nr < N) ? xr[(long)j * C4] : make_float4(0.f, 0.f, 0.f, 0.f);
    }

    #pragma unroll
    for (int r = 0; r < RPT; r++) {
        const float* ap = &s_alpha[(r0 + r) * K];
        const float4 a0 = *(const float4*)ap;        // broadcast LDS.128
        const float4 a1 = *(const float4*)(ap + 4);
        const float  al[K] = {a0.x, a0.y, a0.z, a0.w, a1.x, a1.y, a1.z, a1.w};

        float4 acc = make_float4(0.f, 0.f, 0.f, 0.f);
        #pragma unroll
        for (int p = 0; p < K; p++) {
            const float4 v  = win[(r + p) & (K - 1)];
            const float  aa = al[p];
            acc.x = fmaf(aa, v.x, acc.x);
            acc.y = fmaf(aa, v.y, acc.y);
            acc.z = fmaf(aa, v.z, acc.z);
            acc.w = fmaf(aa, v.w, acc.w);
        }
        orow[(long)r * C4] = acc;

        if (r < RPT - 1) {
            const int nr = nstart + r + K;
            win[r & (K - 1)] =
                (nr < N) ? xr[(long)(r + K) * C4] : make_float4(0.f, 0.f, 0.f, 0.f);
        }
    }
}

extern "C" void kernel_launch(void* const* d_in, const int* in_sizes, int n_in,
                              void* d_out, int out_size)
{
    const float* x    = (const float*)d_in[0];
    const float* dts  = (const float*)d_in[1];
    const void*  mask = d_in[2];
    const float* w    = (const float*)d_in[3];
    const float* beta = (const float*)d_in[4];

    const int BN = in_sizes[1];   // B * N
    const int B  = 8;
    const int N  = BN / B;        // 4096

    dim3 grid(N / TILE_N, B);
    mixer_kernel<<<grid, THREADS>>>(x, dts, mask, w, beta, (float*)d_out, N);
}

// round 2
// speedup vs baseline: 1.0022x; 1.0022x over previous
#include <cuda_runtime.h>
#include <math.h>

#define K        8
#define D        256
#define C4       (D / 4)     // 64 float4 columns
#define TILE_N   32          // rows per block
#define RPT      8           // rows per thread (TILE_N / (THREADS/C4))
#define THREADS  256
#define NEGV     (-1e9f)

// valid_mask may arrive as int32 / uint8(bool) / float32 depending on how the
// harness lowers jnp.bool_. Detect once from word 0 (guaranteed "true" since
// lengths >= N/2).
__device__ __forceinline__ bool mask_at(const void* m, int fmt, long i) {
    if (fmt == 1) return ((const unsigned char*)m)[i] != 0;
    if (fmt == 2) return ((const float*)m)[i] != 0.0f;
    return ((const int*)m)[i] != 0;
}

__global__ __launch_bounds__(THREADS)
void mixer_kernel(const float* __restrict__ x,
                  const float* __restrict__ dts,
                  const void*  __restrict__ maskp,
                  const float* __restrict__ w,
                  const float* __restrict__ beta,
                  float* __restrict__ out,
                  int N)
{
    __shared__ float s_alpha[TILE_N * K];

    const int  b    = blockIdx.y;
    const int  n0   = blockIdx.x * TILE_N;
    const int  tid  = threadIdx.x;
    const long base = (long)b * N;

    // ---- mask format detection (uniform across grid) ----
    const unsigned int w0 = *((const unsigned int*)maskp);
    int fmt = 0;
    if (w0 == 0x01010101u)      fmt = 1;   // uint8 bool
    else if (w0 == 0x3F800000u) fmt = 2;   // float32

    // ================= Phase 1: alpha[TILE_N][K] =================
    if (tid < TILE_N) {
        const int  n      = n0 + tid;
        const bool valid0 = mask_at(maskp, fmt, base + n);
        const float dt0   = dts[base + n];

        float score[K];
        bool  cv[K];
        cv[0]    = valid0;
        score[0] = valid0 ? 0.0f : NEGV;
        #pragma unroll
        for (int p = 1; p < K; p++) {
            const int np = n + p;
            bool  c  = false;
            float td = 0.0f;
            if (np < N) {
                c = valid0 && mask_at(maskp, fmt, base + np);
                if (c) td = fmaxf(dts[base + np] - dt0, 0.0f);
            }
            cv[p]    = c;
            score[p] = c ? -td : NEGV;
        }

        // temporal-decay softmax over offsets
        float m = score[0];
        #pragma unroll
        for (int p = 1; p < K; p++) m = fmaxf(m, score[p]);
        float e[K], es = 0.0f;
        #pragma unroll
        for (int p = 0; p < K; p++) { e[p] = __expf(score[p] - m); es += e[p]; }
        const float inv_es = 1.0f / es;

        // softmax(w) and sigmoid(beta) — tiny, recompute per row
        float wv[K];
        #pragma unroll
        for (int p = 0; p < K; p++) wv[p] = w[p];
        float wm = wv[0];
        #pragma unroll
        for (int p = 1; p < K; p++) wm = fmaxf(wm, wv[p]);
        float we[K], ws = 0.0f;
        #pragma unroll
        for (int p = 0; p < K; p++) { we[p] = __expf(wv[p] - wm); ws += we[p]; }
        const float inv_ws = 1.0f / ws;
        const float bsig   = 1.0f / (1.0f + __expf(-beta[0]));
        const float omb    = 1.0f - bsig;

        float a[K], asum = 0.0f;
        #pragma unroll
        for (int p = 0; p < K; p++) {
            a[p] = cv[p] ? (bsig * we[p] * inv_ws + omb * e[p] * inv_es) : 0.0f;
            asum += a[p];
        }
        const float inv = 1.0f / fmaxf(asum, 1e-8f);
        #pragma unroll
        for (int p = 0; p < K; p++) s_alpha[tid * K + p] = a[p] * inv;
    }
    __syncthreads();

    // ================= Phase 2: weighted sliding-window sum =================
    const int c4     = tid & (C4 - 1);     // float4 column 0..63
    const int g      = tid >> 6;           // row-strip group 0..3
    const int r0     = g * RPT;            // local start row
    const int nstart = n0 + r0;

    const float4* __restrict__ xr =
        (const float4*)x + (base + nstart) * (long)C4 + c4;
    float4* __restrict__ orow =
        (float4*)out + (base + nstart) * (long)C4 + c4;

    // 8-deep register window of x rows at this column (front-batched: MLP=8)
    float4 win[K];
    #pragma unroll
    for (int j = 0; j < K; j++) {
        const int nr = nstart + j;
        win[j] = (nr < N) ? xr[(long)j * C4] : make_float4(0.f, 0.f, 0.f, 0.f);
    }

    #pragma unroll
    for (int r = 0; r < RPT; r++) {
        const float* ap = &s_alpha[(r0 + r) * K];
        const float4 a0 = *(const float4*)ap;        // broadcast LDS.128
        const float4 a1 = *(const float4*)(ap + 4);
        const float  al[K] = {a0.x, a0.y, a0.z, a0.w, a1.x, a1.y, a1.z, a1.w};

        float4 acc = make_float4(0.f, 0.f, 0.f, 0.f);
        #pragma unroll
        for (int p = 0; p < K; p++) {
            const float4 v  = win[(r + p) & (K - 1)];
            const float  aa = al[p];
            acc.x = fmaf(aa, v.x, acc.x);
            acc.y = fmaf(aa, v.y, acc.y);
            acc.z = fmaf(aa, v.z, acc.z);
            acc.w = fmaf(aa, v.w, acc.w);
        }
        orow[(long)r * C4] = acc;

        if (r < RPT - 1) {
            const int nr = nstart + r + K;
            win[r & (K - 1)] =
                (nr < N) ? xr[(long)(r + K) * C4] : make_float4(0.f, 0.f, 0.f, 0.f);
        }
    }
}

extern "C" void kernel_launch(void* const* d_in, const int* in_sizes, int n_in,
                              void* d_out, int out_size)
{
    const float* x    = (const float*)d_in[0];
    const float* dts  = (const float*)d_in[1];
    const void*  mask = d_in[2];
    const float* w    = (const float*)d_in[3];
    const float* beta = (const float*)d_in[4];

    const int BN = in_sizes[1];   // B * N
    const int B  = 8;
    const int N  = BN / B;        // 4096

    dim3 grid(N / TILE_N, B);
    mixer_kernel<<<grid, THREADS>>>(x, dts, mask, w, beta, (float*)d_out, N);
}